// round 1
// baseline (speedup 1.0000x reference)
#include <cuda_runtime.h>
#include <cuda_bf16.h>
#include <cstdint>

// ---------------- problem constants ----------------
#define BB   8
#define NR   4096
#define NK   20
#define FF   256
#define HH   4
#define DD   256
#define KH   80        // NK*HH... no: K*H per (k,h) pairs = 20*4 = 80
#define KNN  8

// ---------------- device scratch (no allocs allowed) ----------------
__device__ float g_ftdst[BB * NK * 1024];    // [b][k][h*256+d]
__device__ float g_V[BB * FF * KH];          // [b][f][kh] , kh = k*4+h  (includes 1/16 scale)
__device__ float g_S[BB * NK * HH * 4];      // [b][k][h][{sumE, sumEx, sumEy, sumEz}]
__device__ float g_kp[BB * NK * 3];
__device__ float g_dk[BB * NK * KNN];
__device__ int   g_idx[BB * NK * KNN];

// ---------------- f32x2 helpers ----------------
__device__ __forceinline__ unsigned long long pack2(float x, float y) {
    unsigned long long r;
    asm("mov.b64 %0, {%1, %2};" : "=l"(r) : "f"(x), "f"(y));
    return r;
}
__device__ __forceinline__ void unpack2(unsigned long long v, float& x, float& y) {
    asm("mov.b64 {%0, %1}, %2;" : "=f"(x), "=f"(y) : "l"(v));
}
__device__ __forceinline__ void fma2(unsigned long long& d, unsigned long long a, unsigned long long b) {
    asm("fma.rn.f32x2 %0, %1, %2, %0;" : "+l"(d) : "l"(a), "l"(b));
}

// ---------------- zero scratch accumulators ----------------
__global__ void k_zero() {
    int i = blockIdx.x * blockDim.x + threadIdx.x;
    if (i < BB * FF * KH) g_V[i] = 0.f;
    int j = i - BB * FF * KH;
    if (j >= 0 && j < BB * NK * HH * 4) g_S[j] = 0.f;
}

// ---------------- A1: ft_dst = h0_kp @ W_src  (160 rows x 1024 cols) ----------------
// grid (16 col-tiles, 8 batches), 256 threads. Each block: 20 rows x 64 cols.
__global__ void __launch_bounds__(256) k_ftdst(const float* __restrict__ h0,
                                               const float* __restrict__ W) {
    __shared__ float hs[NK * FF];  // 20 KB
    int b = blockIdx.y, ct = blockIdx.x;
    for (int i = threadIdx.x; i < NK * FF; i += 256) hs[i] = h0[b * NK * FF + i];
    __syncthreads();
    int cg = threadIdx.x & 63;
    int rgp = threadIdx.x >> 6;      // 0..3, 5 rows each
    int c = ct * 64 + cg;
    float acc[5] = {0.f, 0.f, 0.f, 0.f, 0.f};
#pragma unroll 4
    for (int f = 0; f < 256; f++) {
        float w = W[f * 1024 + c];
#pragma unroll
        for (int q = 0; q < 5; q++) acc[q] += hs[(rgp * 5 + q) * 256 + f] * w;
    }
#pragma unroll
    for (int q = 0; q < 5; q++)
        g_ftdst[(b * NK + rgp * 5 + q) * 1024 + c] = acc[q];
}

// ---------------- A2: V[b,f,k,h] = (1/16) sum_d W[f,h*256+d] * ftdst[b,k,h*256+d] --------
// split over d (4 chunks of 64) with atomicAdd. grid (16 = 4 ftile * 4 dsplit, 8 b).
#define V_SMEM_FLOATS (64 * 257 + NK * 256)
__global__ void __launch_bounds__(256) k_V(const float* __restrict__ W) {
    extern __shared__ float sm[];
    float* ws2 = sm;               // [64 f][257] : [fi*257 + h*64 + dd]
    float* fts2 = sm + 64 * 257;   // [20 k][256] : [k*256 + h*64 + dd]
    int b = blockIdx.y;
    int ft = blockIdx.x >> 2, ds = blockIdx.x & 3;
    int fbase = ft * 64, dbase = ds * 64;
    for (int i = threadIdx.x; i < 64 * 256; i += 256) {
        int fi = i >> 8, rest = i & 255;
        int h = rest >> 6, dd = rest & 63;
        ws2[fi * 257 + rest] = W[(fbase + fi) * 1024 + h * 256 + dbase + dd];
    }
    for (int i = threadIdx.x; i < NK * 256; i += 256) {
        int k = i >> 8, rest = i & 255;
        int h = rest >> 6, dd = rest & 63;
        fts2[i] = g_ftdst[b * 20480 + k * 1024 + h * 256 + dbase + dd];
    }
    __syncthreads();
    int fi = threadIdx.x & 63;
    int h  = threadIdx.x >> 6;    // 0..3
    float acc[NK];
#pragma unroll
    for (int j = 0; j < NK; j++) acc[j] = 0.f;
    const float* wp = ws2 + fi * 257 + h * 64;
    const float* fp = fts2 + h * 64;
#pragma unroll 2
    for (int dd = 0; dd < 64; dd++) {
        float w = wp[dd];
#pragma unroll
        for (int j = 0; j < NK; j++) acc[j] += w * fp[j * 256 + dd];
    }
    float* gv = g_V + b * (FF * KH) + (fbase + fi) * KH + h;
#pragma unroll
    for (int j = 0; j < NK; j++)
        atomicAdd(gv + j * 4, acc[j] * 0.0625f);   // 1/sqrt(256)
}

// ---------------- B: fused  a = h_rec @ V ; exp ; accumulate S0..S3 ----------------
// grid (16 row-chunks of 256, 8 batches), 256 threads, ~155KB dynamic smem.
// thread tile: 2 rows x 5 column-pairs (10 cols), FFMA2 packed over column pairs.
#define ATTN_VS     20480          // 256*80
#define ATTN_HS     (64 * 258)     // padded h tile
#define ATTN_XS     256            // 64 rows * 4
#define ATTN_RED    2560           // 8 warps * 8 cg * 40
#define ATTN_SMEM_FLOATS (ATTN_VS + ATTN_HS + ATTN_XS + ATTN_RED)
__global__ void __launch_bounds__(256, 1) k_attn(const float* __restrict__ h_rec,
                                                 const float* __restrict__ x_rec) {
    extern __shared__ float sm[];
    float* Vs = sm;
    float* hs = sm + ATTN_VS;
    float* xs = hs + ATTN_HS;
    float* red = xs + ATTN_XS;
    int b = blockIdx.y;
    int tid = threadIdx.x;
    const float* gV = g_V + b * (FF * KH);
    for (int i = tid; i < ATTN_VS; i += 256) Vs[i] = gV[i];
    int rg = tid >> 3, cg = tid & 7;
    float s[40];
#pragma unroll
    for (int k = 0; k < 40; k++) s[k] = 0.f;
    int rowbase = blockIdx.x * 256;
    const float* hbase = h_rec + ((size_t)b * NR + rowbase) * FF;
    const float* xbase = x_rec + ((size_t)b * NR + rowbase) * 3;

    for (int st = 0; st < 4; st++) {           // 4 sub-tiles of 64 rows
        __syncthreads();
        const float* gh = hbase + st * 64 * FF;
        for (int i = tid; i < 64 * FF; i += 256) {
            int rr = i >> 8, f = i & 255;
            hs[rr * 258 + f] = gh[i];
        }
        const float* gx = xbase + st * 64 * 3;
        if (tid < 192) xs[(tid / 3) * 4 + (tid % 3)] = gx[tid];
        __syncthreads();

        unsigned long long acc0[5], acc1[5];
#pragma unroll
        for (int i = 0; i < 5; i++) { acc0[i] = 0ull; acc1[i] = 0ull; }
        const float* hp0 = hs + (2 * rg) * 258;
        const float* hp1 = hp0 + 258;
#pragma unroll 4
        for (int f = 0; f < 256; f++) {
            float h0 = hp0[f], h1 = hp1[f];
            unsigned long long H0 = pack2(h0, h0);
            unsigned long long H1 = pack2(h1, h1);
            const unsigned long long* vp = (const unsigned long long*)(Vs + f * KH);
#pragma unroll
            for (int i = 0; i < 5; i++) {
                unsigned long long v = vp[cg + 8 * i];
                fma2(acc0[i], H0, v);
                fma2(acc1[i], H1, v);
            }
        }
        float x00 = xs[2 * rg * 4 + 0], x01 = xs[2 * rg * 4 + 1], x02 = xs[2 * rg * 4 + 2];
        float x10 = xs[(2 * rg + 1) * 4 + 0], x11 = xs[(2 * rg + 1) * 4 + 1], x12 = xs[(2 * rg + 1) * 4 + 2];
#pragma unroll
        for (int i = 0; i < 5; i++) {
            float a0l, a0h, a1l, a1h;
            unpack2(acc0[i], a0l, a0h);
            unpack2(acc1[i], a1l, a1h);
            {
                float e0 = expf(a0l), e1 = expf(a1l);
                int base = (i * 2) * 4;
                s[base + 0] += e0 + e1;
                s[base + 1] += e0 * x00 + e1 * x10;
                s[base + 2] += e0 * x01 + e1 * x11;
                s[base + 3] += e0 * x02 + e1 * x12;
            }
            {
                float e0 = expf(a0h), e1 = expf(a1h);
                int base = (i * 2 + 1) * 4;
                s[base + 0] += e0 + e1;
                s[base + 1] += e0 * x00 + e1 * x10;
                s[base + 2] += e0 * x01 + e1 * x11;
                s[base + 3] += e0 * x02 + e1 * x12;
            }
        }
    }
    // reduce s over the 32 rg-threads sharing a cg: intra-warp (4 rgs) then across 8 warps
#pragma unroll
    for (int k = 0; k < 40; k++) {
        s[k] += __shfl_down_sync(0xffffffffu, s[k], 16);
        s[k] += __shfl_down_sync(0xffffffffu, s[k], 8);
    }
    int lane = tid & 31, w = tid >> 5;
    if (lane < 8) {
        float* rp = red + (w * 8 + lane) * 40;
#pragma unroll
        for (int k = 0; k < 40; k++) rp[k] = s[k];
    }
    __syncthreads();
    for (int v = tid; v < 320; v += 256) {
        int cg2 = v / 40, sidx = v % 40;
        float sum = 0.f;
#pragma unroll
        for (int w2 = 0; w2 < 8; w2++) sum += red[(w2 * 8 + cg2) * 40 + sidx];
        int pair = sidx >> 2, stat = sidx & 3;
        int ii = pair >> 1, sub = pair & 1;
        int col = 2 * (cg2 + 8 * ii) + sub;   // kh index
        atomicAdd(&g_S[b * 320 + col * 4 + stat], sum);
    }
}

// ---------------- pos: kp_pos = mean_h ( S_xyz / S0 ) ----------------
__global__ void k_pos(float* __restrict__ out) {
    int t = threadIdx.x;
    if (t < BB * NK) {
        float p0 = 0.f, p1 = 0.f, p2 = 0.f;
#pragma unroll
        for (int h = 0; h < HH; h++) {
            const float* S = g_S + t * 16 + h * 4;
            float inv = 1.f / S[0];
            p0 += S[1] * inv;
            p1 += S[2] * inv;
            p2 += S[3] * inv;
        }
        p0 *= 0.25f; p1 *= 0.25f; p2 *= 0.25f;
        g_kp[t * 3 + 0] = p0; g_kp[t * 3 + 1] = p1; g_kp[t * 3 + 2] = p2;
        out[t * 3 + 0] = p0;  out[t * 3 + 1] = p1;  out[t * 3 + 2] = p2;
    }
}

// ---------------- C: per-(b,k) top-8 nearest rec atoms ----------------
__global__ void __launch_bounds__(256) k_topk(const float* __restrict__ x_rec) {
    __shared__ float sd[256 * KNN];
    __shared__ int   si[256 * KNN];
    int bk = blockIdx.x, b = bk / NK, tid = threadIdx.x;
    float px = g_kp[bk * 3 + 0], py = g_kp[bk * 3 + 1], pz = g_kp[bk * 3 + 2];
    float bd[KNN]; int bi[KNN];
#pragma unroll
    for (int j = 0; j < KNN; j++) { bd[j] = 3.4e38f; bi[j] = 0x7fffffff; }
    const float* xb = x_rec + (size_t)b * NR * 3;
    for (int r = tid; r < NR; r += 256) {
        float dx = xb[r * 3 + 0] - px;
        float dy = xb[r * 3 + 1] - py;
        float dz = xb[r * 3 + 2] - pz;
        float d2 = dx * dx + dy * dy + dz * dz;
        if (d2 < bd[KNN - 1]) {
            int p = KNN - 1;
            while (p > 0 && d2 < bd[p - 1]) { bd[p] = bd[p - 1]; bi[p] = bi[p - 1]; p--; }
            bd[p] = d2; bi[p] = r;
        }
    }
#pragma unroll
    for (int j = 0; j < KNN; j++) { sd[tid * KNN + j] = bd[j]; si[tid * KNN + j] = bi[j]; }
    for (int stride = 128; stride >= 1; stride >>= 1) {
        __syncthreads();
        if (tid < stride) {
            float od[KNN]; int oi[KNN];
            int ia = 0, ib = 0;
#pragma unroll
            for (int o = 0; o < KNN; o++) {
                float da = sd[tid * KNN + ia], db = sd[(tid + stride) * KNN + ib];
                int xa = si[tid * KNN + ia], xb2 = si[(tid + stride) * KNN + ib];
                bool ta = (da < db) || (da == db && xa < xb2);
                if (ta) { od[o] = da; oi[o] = xa; ia++; }
                else    { od[o] = db; oi[o] = xb2; ib++; }
            }
#pragma unroll
            for (int o = 0; o < KNN; o++) { sd[tid * KNN + o] = od[o]; si[tid * KNN + o] = oi[o]; }
        }
    }
    __syncthreads();
    if (tid < KNN) {
        g_dk[bk * KNN + tid] = sqrtf(sd[tid]);
        g_idx[bk * KNN + tid] = si[tid];
    }
}

// ---------------- D: gather kNN mean -> MLP -> SiLU -> LayerNorm ----------------
__global__ void __launch_bounds__(256) k_mlp(const float* __restrict__ h_rec,
                                             const float* __restrict__ W_mlp,
                                             const float* __restrict__ b_mlp,
                                             const float* __restrict__ gamma,
                                             const float* __restrict__ beta,
                                             float* __restrict__ out) {
    __shared__ float hm[FF];
    __shared__ float dk8[KNN];
    __shared__ int   id8[KNN];
    __shared__ float rbuf[16];
    __shared__ float mv[2];
    int bk = blockIdx.x, b = bk / NK, j = threadIdx.x;
    if (j < KNN) { dk8[j] = g_dk[bk * KNN + j]; id8[j] = g_idx[bk * KNN + j]; }
    __syncthreads();
    float a = 0.f;
#pragma unroll
    for (int t = 0; t < KNN; t++)
        a += h_rec[((size_t)b * NR + id8[t]) * FF + j];
    hm[j] = a * 0.125f;
    __syncthreads();
    float y = b_mlp[j];
#pragma unroll 4
    for (int i = 0; i < FF; i++) y += hm[i] * W_mlp[i * FF + j];
#pragma unroll
    for (int t = 0; t < KNN; t++) y += dk8[t] * W_mlp[(FF + t) * FF + j];
    y = y / (1.f + expf(-y));   // SiLU
    // LayerNorm over 256 features
    float s1 = y, s2 = y * y;
#pragma unroll
    for (int d = 16; d; d >>= 1) {
        s1 += __shfl_down_sync(0xffffffffu, s1, d);
        s2 += __shfl_down_sync(0xffffffffu, s2, d);
    }
    int lane = j & 31, w = j >> 5;
    if (lane == 0) { rbuf[w] = s1; rbuf[8 + w] = s2; }
    __syncthreads();
    if (j == 0) {
        float sa = 0.f, sb = 0.f;
#pragma unroll
        for (int w2 = 0; w2 < 8; w2++) { sa += rbuf[w2]; sb += rbuf[8 + w2]; }
        float mu = sa * (1.f / 256.f);
        mv[0] = mu;
        mv[1] = sb * (1.f / 256.f) - mu * mu;
    }
    __syncthreads();
    float mu = mv[0];
    float inv = rsqrtf(mv[1] + 1e-5f);
    out[BB * NK * 3 + bk * FF + j] = (y - mu) * inv * gamma[j] + beta[j];
}

// ---------------- launch ----------------
extern "C" void kernel_launch(void* const* d_in, const int* in_sizes, int n_in,
                              void* d_out, int out_size) {
    const float* h_rec = (const float*)d_in[0];
    const float* x_rec = (const float*)d_in[1];
    const float* h0_kp = (const float*)d_in[2];
    const float* W_src = (const float*)d_in[3];
    const float* W_mlp = (const float*)d_in[4];
    const float* b_mlp = (const float*)d_in[5];
    const float* gamma = (const float*)d_in[6];
    const float* beta  = (const float*)d_in[7];
    float* out = (float*)d_out;

    const int attn_smem = ATTN_SMEM_FLOATS * 4;
    const int v_smem = V_SMEM_FLOATS * 4;
    cudaFuncSetAttribute(k_attn, cudaFuncAttributeMaxDynamicSharedMemorySize, attn_smem);
    cudaFuncSetAttribute(k_V, cudaFuncAttributeMaxDynamicSharedMemorySize, v_smem);

    int zero_total = BB * FF * KH + BB * NK * HH * 4;
    k_zero<<<(zero_total + 255) / 256, 256>>>();
    k_ftdst<<<dim3(16, BB), 256>>>(h0_kp, W_src);
    k_V<<<dim3(16, BB), 256, v_smem>>>(W_src);
    k_attn<<<dim3(16, BB), 256, attn_smem>>>(h_rec, x_rec);
    k_pos<<<1, 192>>>(out);
    k_topk<<<BB * NK, 256>>>(x_rec);
    k_mlp<<<BB * NK, 256>>>(h_rec, W_mlp, b_mlp, gamma, beta, out);
}

// round 2
// speedup vs baseline: 1.1253x; 1.1253x over previous
#include <cuda_runtime.h>
#include <cuda_bf16.h>
#include <cstdint>

// ---------------- problem constants ----------------
#define BB   8
#define NR   4096
#define NK   20
#define FF   256
#define HH   4
#define KH   80        // NK*HH column count of fused V
#define KNN  8

// ---------------- device scratch ----------------
__device__ float g_ftdst[BB * NK * 1024];    // [b][k][h*256+d]
__device__ float g_V[BB * FF * KH];          // [b][f][kh], kh = k*4+h  (scaled 1/16)
__device__ float g_S[BB * NK * HH * 4];      // [b][k][h][{sumE, sumEx, sumEy, sumEz}]

// ---------------- f32x2 helpers ----------------
__device__ __forceinline__ unsigned long long pack2(float x, float y) {
    unsigned long long r;
    asm("mov.b64 %0, {%1, %2};" : "=l"(r) : "f"(x), "f"(y));
    return r;
}
__device__ __forceinline__ void unpack2(unsigned long long v, float& x, float& y) {
    asm("mov.b64 {%0, %1}, %2;" : "=f"(x), "=f"(y) : "l"(v));
}
__device__ __forceinline__ void fma2(unsigned long long& d, unsigned long long a, unsigned long long b) {
    asm("fma.rn.f32x2 %0, %1, %2, %0;" : "+l"(d) : "l"(a), "l"(b));
}

// ---------------- A1: ft_dst = h0_kp @ W_src  (+ scratch zeroing) ----------------
__global__ void __launch_bounds__(256) k_ftdst(const float* __restrict__ h0,
                                               const float* __restrict__ W) {
    __shared__ float hs[NK * FF];
    int b = blockIdx.y, ct = blockIdx.x;
    // fold zeroing of accumulators into this kernel (ct==0 blocks)
    if (ct == 0) {
        for (int i = threadIdx.x; i < FF * KH; i += 256) g_V[b * FF * KH + i] = 0.f;
        for (int i = threadIdx.x; i < NK * HH * 4; i += 256) g_S[b * NK * HH * 4 + i] = 0.f;
    }
    for (int i = threadIdx.x; i < NK * FF; i += 256) hs[i] = h0[b * NK * FF + i];
    __syncthreads();
    int cg = threadIdx.x & 63;
    int rgp = threadIdx.x >> 6;
    int c = ct * 64 + cg;
    float acc[5] = {0.f, 0.f, 0.f, 0.f, 0.f};
#pragma unroll 4
    for (int f = 0; f < 256; f++) {
        float w = W[f * 1024 + c];
#pragma unroll
        for (int q = 0; q < 5; q++) acc[q] += hs[(rgp * 5 + q) * 256 + f] * w;
    }
#pragma unroll
    for (int q = 0; q < 5; q++)
        g_ftdst[(b * NK + rgp * 5 + q) * 1024 + c] = acc[q];
}

// ---------------- A2: V[b,f,kh] = (1/16) sum_d W[f,h*256+d] * ftdst[b,k,h*256+d] ----
#define V_SMEM_FLOATS (64 * 257 + NK * 256)
__global__ void __launch_bounds__(256) k_V(const float* __restrict__ W) {
    extern __shared__ float sm[];
    float* ws2 = sm;
    float* fts2 = sm + 64 * 257;
    int b = blockIdx.y;
    int ft = blockIdx.x >> 2, ds = blockIdx.x & 3;
    int fbase = ft * 64, dbase = ds * 64;
    for (int i = threadIdx.x; i < 64 * 256; i += 256) {
        int fi = i >> 8, rest = i & 255;
        int h = rest >> 6, dd = rest & 63;
        ws2[fi * 257 + rest] = W[(fbase + fi) * 1024 + h * 256 + dbase + dd];
    }
    for (int i = threadIdx.x; i < NK * 256; i += 256) {
        int rest = i & 255;
        int h = rest >> 6, dd = rest & 63;
        int k = i >> 8;
        fts2[i] = g_ftdst[b * 20480 + k * 1024 + h * 256 + dbase + dd];
    }
    __syncthreads();
    int fi = threadIdx.x & 63;
    int h  = threadIdx.x >> 6;
    float acc[NK];
#pragma unroll
    for (int j = 0; j < NK; j++) acc[j] = 0.f;
    const float* wp = ws2 + fi * 257 + h * 64;
    const float* fp = fts2 + h * 64;
#pragma unroll 2
    for (int dd = 0; dd < 64; dd++) {
        float w = wp[dd];
#pragma unroll
        for (int j = 0; j < NK; j++) acc[j] += w * fp[j * 256 + dd];
    }
    float* gv = g_V + b * (FF * KH) + (fbase + fi) * KH + h;
#pragma unroll
    for (int j = 0; j < NK; j++)
        atomicAdd(gv + j * 4, acc[j] * 0.0625f);
}

// ---------------- B: fused  a = h_rec @ V ; exp ; accumulate 4 moments ----------------
// grid (32, 8), 256 threads, 2 CTAs/SM. Each block: 128 rows (2 subtiles x 64).
// Thread: 2 rows x 5 column-pairs. V permuted in smem: f*96 + cg*12 + j (j<10).
#define ATTN_VS   (256 * 96)     // 24576 floats = 98304 B
#define ATTN_RED  2560           // 8 warps * 8 cg * 40
#define ATTN_SMEM_FLOATS (ATTN_VS + ATTN_RED)
__global__ void __launch_bounds__(256, 2) k_attn(const float* __restrict__ h_rec,
                                                 const float* __restrict__ x_rec) {
    extern __shared__ float sm[];
    float* Vsp = sm;
    float* red = sm + ATTN_VS;
    int b = blockIdx.y;
    int tid = threadIdx.x;
    int lane = tid & 31, w = tid >> 5;
    int rg = tid >> 3, cg = tid & 7;

    // load + permute V: thread's 10 columns contiguous (padded to 12)
    const float* gV = g_V + b * (FF * KH);
    for (int t = tid; t < FF * KH; t += 256) {
        int f = t / 80, q = t % 80;
        int c2 = q / 10, j = q % 10;
        int ip = j >> 1, sub = j & 1;
        int c = ((c2 + 8 * ip) << 1) | sub;
        Vsp[f * 96 + c2 * 12 + j] = gV[f * 80 + c];
    }
    for (int t = tid; t < ATTN_RED; t += 256) red[t] = 0.f;
    __syncthreads();

    int rowbase = blockIdx.x * 128;
    const float* hblk = h_rec + ((size_t)b * NR + rowbase) * FF;

#pragma unroll 1
    for (int st = 0; st < 2; st++) {
        int row0 = st * 64 + 2 * rg;
        const float4* hp0 = (const float4*)(hblk + (size_t)row0 * FF);
        const float4* hp1 = (const float4*)(hblk + (size_t)(row0 + 1) * FF);

        unsigned long long acc0[5], acc1[5];
#pragma unroll
        for (int i = 0; i < 5; i++) { acc0[i] = 0ull; acc1[i] = 0ull; }

        const char* vbase = (const char*)(Vsp + cg * 12);
#pragma unroll 2
        for (int f4 = 0; f4 < 64; f4++) {
            float4 a0 = __ldg(hp0 + f4);
            float4 a1 = __ldg(hp1 + f4);
#pragma unroll
            for (int e = 0; e < 4; e++) {
                float h0 = (e == 0) ? a0.x : (e == 1) ? a0.y : (e == 2) ? a0.z : a0.w;
                float h1 = (e == 0) ? a1.x : (e == 1) ? a1.y : (e == 2) ? a1.z : a1.w;
                unsigned long long H0 = pack2(h0, h0);
                unsigned long long H1 = pack2(h1, h1);
                const ulonglong2* vp = (const ulonglong2*)(vbase + (size_t)(f4 * 4 + e) * 384);
                ulonglong2 v01 = vp[0];
                ulonglong2 v23 = vp[1];
                unsigned long long v4 = *(const unsigned long long*)(vp + 2);
                fma2(acc0[0], H0, v01.x); fma2(acc1[0], H1, v01.x);
                fma2(acc0[1], H0, v01.y); fma2(acc1[1], H1, v01.y);
                fma2(acc0[2], H0, v23.x); fma2(acc1[2], H1, v23.x);
                fma2(acc0[3], H0, v23.y); fma2(acc1[3], H1, v23.y);
                fma2(acc0[4], H0, v4);    fma2(acc1[4], H1, v4);
            }
        }

        // epilogue: exp + 4 moments, warp-reduce over the 4 rg-threads per cg
        const float* xp = x_rec + ((size_t)b * NR + rowbase + row0) * 3;
        float x00 = xp[0], x01 = xp[1], x02 = xp[2];
        float x10 = xp[3], x11 = xp[4], x12 = xp[5];
#pragma unroll
        for (int i = 0; i < 5; i++) {
            float a0l, a0h, a1l, a1h;
            unpack2(acc0[i], a0l, a0h);
            unpack2(acc1[i], a1l, a1h);
#pragma unroll
            for (int sub = 0; sub < 2; sub++) {
                float e0 = expf(sub ? a0h : a0l);
                float e1 = expf(sub ? a1h : a1l);
                float v0 = e0 + e1;
                float v1 = e0 * x00 + e1 * x10;
                float v2 = e0 * x01 + e1 * x11;
                float v3 = e0 * x02 + e1 * x12;
#pragma unroll
                for (int d = 16; d >= 8; d >>= 1) {
                    v0 += __shfl_down_sync(0xffffffffu, v0, d);
                    v1 += __shfl_down_sync(0xffffffffu, v1, d);
                    v2 += __shfl_down_sync(0xffffffffu, v2, d);
                    v3 += __shfl_down_sync(0xffffffffu, v3, d);
                }
                if (lane < 8) {
                    float* rp = red + w * 320 + cg * 40 + (2 * i + sub) * 4;
                    rp[0] += v0; rp[1] += v1; rp[2] += v2; rp[3] += v3;
                }
            }
        }
    }
    __syncthreads();
    // final cross-warp reduce + global atomic
    for (int v = tid; v < 320; v += 256) {
        int cg2 = v / 40, sidx = v % 40;
        float sum = 0.f;
#pragma unroll
        for (int w2 = 0; w2 < 8; w2++) sum += red[w2 * 320 + cg2 * 40 + sidx];
        int pair = sidx >> 2, stat = sidx & 3;
        int ii = pair >> 1, sub = pair & 1;
        int col = 2 * (cg2 + 8 * ii) + sub;
        atomicAdd(&g_S[b * 320 + col * 4 + stat], sum);
    }
}

// ---------------- tail: kp_pos + top-8 + gather/MLP/SiLU/LayerNorm (fused) --------
__global__ void __launch_bounds__(256) k_tail(const float* __restrict__ x_rec,
                                              const float* __restrict__ h_rec,
                                              const float* __restrict__ W_mlp,
                                              const float* __restrict__ b_mlp,
                                              const float* __restrict__ gamma,
                                              const float* __restrict__ beta,
                                              float* __restrict__ out) {
    __shared__ float sd[256 * KNN];
    __shared__ int   si[256 * KNN];
    __shared__ float kpos[3];
    __shared__ float hm[FF];
    __shared__ float dk8[KNN];
    __shared__ int   id8[KNN];
    __shared__ float rbuf[16];
    __shared__ float mv[2];
    int bk = blockIdx.x, b = bk / NK, tid = threadIdx.x;

    // kp_pos from moments
    if (tid == 0) {
        float p0 = 0.f, p1 = 0.f, p2 = 0.f;
#pragma unroll
        for (int h = 0; h < HH; h++) {
            const float* S = g_S + bk * 16 + h * 4;
            float inv = 1.f / S[0];
            p0 += S[1] * inv; p1 += S[2] * inv; p2 += S[3] * inv;
        }
        p0 *= 0.25f; p1 *= 0.25f; p2 *= 0.25f;
        kpos[0] = p0; kpos[1] = p1; kpos[2] = p2;
        out[bk * 3 + 0] = p0; out[bk * 3 + 1] = p1; out[bk * 3 + 2] = p2;
    }
    __syncthreads();
    float px = kpos[0], py = kpos[1], pz = kpos[2];

    // per-thread top-8 then merge tree
    float bd[KNN]; int bi[KNN];
#pragma unroll
    for (int j = 0; j < KNN; j++) { bd[j] = 3.4e38f; bi[j] = 0x7fffffff; }
    const float* xb = x_rec + (size_t)b * NR * 3;
    for (int r = tid; r < NR; r += 256) {
        float dx = xb[r * 3 + 0] - px;
        float dy = xb[r * 3 + 1] - py;
        float dz = xb[r * 3 + 2] - pz;
        float d2 = dx * dx + dy * dy + dz * dz;
        if (d2 < bd[KNN - 1]) {
            int p = KNN - 1;
            while (p > 0 && d2 < bd[p - 1]) { bd[p] = bd[p - 1]; bi[p] = bi[p - 1]; p--; }
            bd[p] = d2; bi[p] = r;
        }
    }
#pragma unroll
    for (int j = 0; j < KNN; j++) { sd[tid * KNN + j] = bd[j]; si[tid * KNN + j] = bi[j]; }
    for (int stride = 128; stride >= 1; stride >>= 1) {
        __syncthreads();
        if (tid < stride) {
            float od[KNN]; int oi[KNN];
            int ia = 0, ib = 0;
#pragma unroll
            for (int o = 0; o < KNN; o++) {
                float da = sd[tid * KNN + ia], db = sd[(tid + stride) * KNN + ib];
                int xa = si[tid * KNN + ia], xb2 = si[(tid + stride) * KNN + ib];
                bool ta = (da < db) || (da == db && xa < xb2);
                if (ta) { od[o] = da; oi[o] = xa; ia++; }
                else    { od[o] = db; oi[o] = xb2; ib++; }
            }
#pragma unroll
            for (int o = 0; o < KNN; o++) { sd[tid * KNN + o] = od[o]; si[tid * KNN + o] = oi[o]; }
        }
    }
    __syncthreads();
    if (tid < KNN) { dk8[tid] = sqrtf(sd[tid]); id8[tid] = si[tid]; }
    __syncthreads();

    // gather kNN mean
    int j = tid;
    float a = 0.f;
#pragma unroll
    for (int t = 0; t < KNN; t++)
        a += h_rec[((size_t)b * NR + id8[t]) * FF + j];
    hm[j] = a * 0.125f;
    __syncthreads();

    // MLP + SiLU
    float y = b_mlp[j];
#pragma unroll 16
    for (int i = 0; i < FF; i++) y += hm[i] * W_mlp[i * FF + j];
#pragma unroll
    for (int t = 0; t < KNN; t++) y += dk8[t] * W_mlp[(FF + t) * FF + j];
    y = y / (1.f + expf(-y));

    // LayerNorm
    float s1 = y, s2 = y * y;
#pragma unroll
    for (int d = 16; d; d >>= 1) {
        s1 += __shfl_down_sync(0xffffffffu, s1, d);
        s2 += __shfl_down_sync(0xffffffffu, s2, d);
    }
    int lane = j & 31, w = j >> 5;
    if (lane == 0) { rbuf[w] = s1; rbuf[8 + w] = s2; }
    __syncthreads();
    if (j == 0) {
        float sa = 0.f, sb = 0.f;
#pragma unroll
        for (int w2 = 0; w2 < 8; w2++) { sa += rbuf[w2]; sb += rbuf[8 + w2]; }
        float mu = sa * (1.f / 256.f);
        mv[0] = mu;
        mv[1] = sb * (1.f / 256.f) - mu * mu;
    }
    __syncthreads();
    float mu = mv[0];
    float inv = rsqrtf(mv[1] + 1e-5f);
    out[BB * NK * 3 + bk * FF + j] = (y - mu) * inv * gamma[j] + beta[j];
}

// ---------------- launch ----------------
extern "C" void kernel_launch(void* const* d_in, const int* in_sizes, int n_in,
                              void* d_out, int out_size) {
    const float* h_rec = (const float*)d_in[0];
    const float* x_rec = (const float*)d_in[1];
    const float* h0_kp = (const float*)d_in[2];
    const float* W_src = (const float*)d_in[3];
    const float* W_mlp = (const float*)d_in[4];
    const float* b_mlp = (const float*)d_in[5];
    const float* gamma = (const float*)d_in[6];
    const float* beta  = (const float*)d_in[7];
    float* out = (float*)d_out;

    const int attn_smem = ATTN_SMEM_FLOATS * 4;
    const int v_smem = V_SMEM_FLOATS * 4;
    cudaFuncSetAttribute(k_attn, cudaFuncAttributeMaxDynamicSharedMemorySize, attn_smem);
    cudaFuncSetAttribute(k_V, cudaFuncAttributeMaxDynamicSharedMemorySize, v_smem);

    k_ftdst<<<dim3(16, BB), 256>>>(h0_kp, W_src);
    k_V<<<dim3(16, BB), 256, v_smem>>>(W_src);
    k_attn<<<dim3(32, BB), 256, attn_smem>>>(h_rec, x_rec);
    k_tail<<<BB * NK, 256>>>(x_rec, h_rec, W_mlp, b_mlp, gamma, beta, out);
}

// round 3
// speedup vs baseline: 1.1566x; 1.0278x over previous
#include <cuda_runtime.h>
#include <cuda_bf16.h>
#include <cstdint>

// ---------------- problem constants ----------------
#define BB   8
#define NR   4096
#define NK   20
#define FF   256
#define HH   4
#define KH   80        // NK*HH column count of fused V
#define KNN  8

// ---------------- device scratch ----------------
__device__ float g_ftdst[BB * NK * 1024];    // [b][k][h*256+d]
__device__ float g_V[BB * FF * KH];          // [b][f][kh], kh = k*4+h  (scaled 1/16)
__device__ float g_S[BB * NK * HH * 4];      // [b][k][h][{sumE, sumEx, sumEy, sumEz}]

// ---------------- f32x2 helpers ----------------
__device__ __forceinline__ unsigned long long pack2(float x, float y) {
    unsigned long long r;
    asm("mov.b64 %0, {%1, %2};" : "=l"(r) : "f"(x), "f"(y));
    return r;
}
__device__ __forceinline__ void unpack2(unsigned long long v, float& x, float& y) {
    asm("mov.b64 {%0, %1}, %2;" : "=f"(x), "=f"(y) : "l"(v));
}
__device__ __forceinline__ void fma2(unsigned long long& d, unsigned long long a, unsigned long long b) {
    asm("fma.rn.f32x2 %0, %1, %2, %0;" : "+l"(d) : "l"(a), "l"(b));
}

// ---------------- A1: ft_dst = h0_kp @ W_src (smem-staged W tile) ----------------
#define FT_SMEM_FLOATS (NK * FF + 256 * 65)
__global__ void __launch_bounds__(256) k_ftdst(const float* __restrict__ h0,
                                               const float* __restrict__ W) {
    extern __shared__ float sm[];
    float* hs = sm;             // [20][256]
    float* ws = sm + NK * FF;   // [256][65] padded
    int b = blockIdx.y, ct = blockIdx.x;
    // zero g_V (needed before k_V atomics)
    if (ct == 0) {
        for (int i = threadIdx.x; i < FF * KH; i += 256) g_V[b * FF * KH + i] = 0.f;
    }
    for (int i = threadIdx.x; i < NK * FF; i += 256) hs[i] = h0[b * NK * FF + i];
    // coalesced W tile load: rows f, cols ct*64..+64
#pragma unroll 8
    for (int i = threadIdx.x; i < 256 * 64; i += 256) {
        int f = i >> 6, c = i & 63;
        ws[f * 65 + c] = W[f * 1024 + ct * 64 + c];
    }
    __syncthreads();
    int cg = threadIdx.x & 63;
    int rgp = threadIdx.x >> 6;
    float acc[5] = {0.f, 0.f, 0.f, 0.f, 0.f};
#pragma unroll 8
    for (int f = 0; f < 256; f++) {
        float w = ws[f * 65 + cg];
#pragma unroll
        for (int q = 0; q < 5; q++) acc[q] += hs[(rgp * 5 + q) * 256 + f] * w;
    }
    int c = ct * 64 + cg;
#pragma unroll
    for (int q = 0; q < 5; q++)
        g_ftdst[(b * NK + rgp * 5 + q) * 1024 + c] = acc[q];
}

// ---------------- A2: V[b,f,kh] = (1/16) sum_d W[f,h*256+d] * ftdst[b,k,h*256+d] ----
#define V_SMEM_FLOATS (64 * 257 + NK * 256)
__global__ void __launch_bounds__(256) k_V(const float* __restrict__ W) {
    extern __shared__ float sm[];
    float* ws2 = sm;
    float* fts2 = sm + 64 * 257;
    int b = blockIdx.y;
    int ft = blockIdx.x >> 2, ds = blockIdx.x & 3;
    int fbase = ft * 64, dbase = ds * 64;
#pragma unroll 4
    for (int i = threadIdx.x; i < 64 * 256; i += 256) {
        int fi = i >> 8, rest = i & 255;
        int h = rest >> 6, dd = rest & 63;
        ws2[fi * 257 + rest] = W[(fbase + fi) * 1024 + h * 256 + dbase + dd];
    }
#pragma unroll 4
    for (int i = threadIdx.x; i < NK * 256; i += 256) {
        int rest = i & 255;
        int h = rest >> 6, dd = rest & 63;
        int k = i >> 8;
        fts2[i] = g_ftdst[b * 20480 + k * 1024 + h * 256 + dbase + dd];
    }
    __syncthreads();
    int fi = threadIdx.x & 63;
    int h  = threadIdx.x >> 6;
    float acc[NK];
#pragma unroll
    for (int j = 0; j < NK; j++) acc[j] = 0.f;
    const float* wp = ws2 + fi * 257 + h * 64;
    const float* fp = fts2 + h * 64;
#pragma unroll 2
    for (int dd = 0; dd < 64; dd++) {
        float w = wp[dd];
#pragma unroll
        for (int j = 0; j < NK; j++) acc[j] += w * fp[j * 256 + dd];
    }
    float* gv = g_V + b * (FF * KH) + (fbase + fi) * KH + h;
#pragma unroll
    for (int j = 0; j < NK; j++)
        atomicAdd(gv + j * 4, acc[j] * 0.0625f);
}

// ---------------- zero g_S (3rd launch so k_attn is the profiled 4th) ----------------
__global__ void k_zeroS() {
    int i = blockIdx.x * blockDim.x + threadIdx.x;
    if (i < BB * NK * HH * 4) g_S[i] = 0.f;
}

// ---------------- B: fused  a = h_rec @ V ; exp ; 4 moments ----------------
#define ATTN_VS   (256 * 96)
#define ATTN_RED  2560
#define ATTN_SMEM_FLOATS (ATTN_VS + ATTN_RED)
__global__ void __launch_bounds__(256, 2) k_attn(const float* __restrict__ h_rec,
                                                 const float* __restrict__ x_rec) {
    extern __shared__ float sm[];
    float* Vsp = sm;
    float* red = sm + ATTN_VS;
    int b = blockIdx.y;
    int tid = threadIdx.x;
    int lane = tid & 31, w = tid >> 5;
    int rg = tid >> 3, cg = tid & 7;

    const float* gV = g_V + b * (FF * KH);
    for (int t = tid; t < FF * KH; t += 256) {
        int f = t / 80, q = t % 80;
        int c2 = q / 10, j = q % 10;
        int ip = j >> 1, sub = j & 1;
        int c = ((c2 + 8 * ip) << 1) | sub;
        Vsp[f * 96 + c2 * 12 + j] = gV[f * 80 + c];
    }
    for (int t = tid; t < ATTN_RED; t += 256) red[t] = 0.f;
    __syncthreads();

    int rowbase = blockIdx.x * 128;
    const float* hblk = h_rec + ((size_t)b * NR + rowbase) * FF;

#pragma unroll 1
    for (int st = 0; st < 2; st++) {
        int row0 = st * 64 + 2 * rg;
        const float4* hp0 = (const float4*)(hblk + (size_t)row0 * FF);
        const float4* hp1 = (const float4*)(hblk + (size_t)(row0 + 1) * FF);

        unsigned long long acc0[5], acc1[5];
#pragma unroll
        for (int i = 0; i < 5; i++) { acc0[i] = 0ull; acc1[i] = 0ull; }

        const char* vbase = (const char*)(Vsp + cg * 12);
        float4 a0 = __ldg(hp0), a1 = __ldg(hp1);
#pragma unroll 2
        for (int f4 = 0; f4 < 64; f4++) {
            float4 n0, n1;
            if (f4 < 63) { n0 = __ldg(hp0 + f4 + 1); n1 = __ldg(hp1 + f4 + 1); }
#pragma unroll
            for (int e = 0; e < 4; e++) {
                float h0 = (e == 0) ? a0.x : (e == 1) ? a0.y : (e == 2) ? a0.z : a0.w;
                float h1 = (e == 0) ? a1.x : (e == 1) ? a1.y : (e == 2) ? a1.z : a1.w;
                unsigned long long H0 = pack2(h0, h0);
                unsigned long long H1 = pack2(h1, h1);
                const ulonglong2* vp = (const ulonglong2*)(vbase + (size_t)(f4 * 4 + e) * 384);
                ulonglong2 v01 = vp[0];
                ulonglong2 v23 = vp[1];
                unsigned long long v4 = *(const unsigned long long*)(vp + 2);
                fma2(acc0[0], H0, v01.x); fma2(acc1[0], H1, v01.x);
                fma2(acc0[1], H0, v01.y); fma2(acc1[1], H1, v01.y);
                fma2(acc0[2], H0, v23.x); fma2(acc1[2], H1, v23.x);
                fma2(acc0[3], H0, v23.y); fma2(acc1[3], H1, v23.y);
                fma2(acc0[4], H0, v4);    fma2(acc1[4], H1, v4);
            }
            a0 = n0; a1 = n1;
        }

        const float* xp = x_rec + ((size_t)b * NR + rowbase + row0) * 3;
        float x00 = xp[0], x01 = xp[1], x02 = xp[2];
        float x10 = xp[3], x11 = xp[4], x12 = xp[5];
#pragma unroll
        for (int i = 0; i < 5; i++) {
            float a0l, a0h, a1l, a1h;
            unpack2(acc0[i], a0l, a0h);
            unpack2(acc1[i], a1l, a1h);
#pragma unroll
            for (int sub = 0; sub < 2; sub++) {
                float e0 = expf(sub ? a0h : a0l);
                float e1 = expf(sub ? a1h : a1l);
                float v0 = e0 + e1;
                float v1 = e0 * x00 + e1 * x10;
                float v2 = e0 * x01 + e1 * x11;
                float v3 = e0 * x02 + e1 * x12;
#pragma unroll
                for (int d = 16; d >= 8; d >>= 1) {
                    v0 += __shfl_down_sync(0xffffffffu, v0, d);
                    v1 += __shfl_down_sync(0xffffffffu, v1, d);
                    v2 += __shfl_down_sync(0xffffffffu, v2, d);
                    v3 += __shfl_down_sync(0xffffffffu, v3, d);
                }
                if (lane < 8) {
                    float* rp = red + w * 320 + cg * 40 + (2 * i + sub) * 4;
                    rp[0] += v0; rp[1] += v1; rp[2] += v2; rp[3] += v3;
                }
            }
        }
    }
    __syncthreads();
    for (int v = tid; v < 320; v += 256) {
        int cg2 = v / 40, sidx = v % 40;
        float sum = 0.f;
#pragma unroll
        for (int w2 = 0; w2 < 8; w2++) sum += red[w2 * 320 + cg2 * 40 + sidx];
        int pair = sidx >> 2, stat = sidx & 3;
        int ii = pair >> 1, sub = pair & 1;
        int col = 2 * (cg2 + 8 * ii) + sub;
        atomicAdd(&g_S[b * 320 + col * 4 + stat], sum);
    }
}

// ---------------- tail: kp_pos + top-8 + gather/MLP/SiLU/LayerNorm ----------------
__global__ void __launch_bounds__(256) k_tail(const float* __restrict__ x_rec,
                                              const float* __restrict__ h_rec,
                                              const float* __restrict__ W_mlp,
                                              const float* __restrict__ b_mlp,
                                              const float* __restrict__ gamma,
                                              const float* __restrict__ beta,
                                              float* __restrict__ out) {
    __shared__ float sd[256 * KNN];
    __shared__ int   si[256 * KNN];
    __shared__ float kpos[3];
    __shared__ float hm[FF];
    __shared__ float dk8[KNN];
    __shared__ int   id8[KNN];
    __shared__ float rbuf[16];
    __shared__ float mv[2];
    int bk = blockIdx.x, b = bk / NK, tid = threadIdx.x;

    if (tid == 0) {
        float p0 = 0.f, p1 = 0.f, p2 = 0.f;
#pragma unroll
        for (int h = 0; h < HH; h++) {
            const float* S = g_S + bk * 16 + h * 4;
            float inv = 1.f / S[0];
            p0 += S[1] * inv; p1 += S[2] * inv; p2 += S[3] * inv;
        }
        p0 *= 0.25f; p1 *= 0.25f; p2 *= 0.25f;
        kpos[0] = p0; kpos[1] = p1; kpos[2] = p2;
        out[bk * 3 + 0] = p0; out[bk * 3 + 1] = p1; out[bk * 3 + 2] = p2;
    }
    __syncthreads();
    float px = kpos[0], py = kpos[1], pz = kpos[2];

    // per-thread top-8 with batched distance computation (high MLP)
    float bd[KNN]; int bi[KNN];
#pragma unroll
    for (int j = 0; j < KNN; j++) { bd[j] = 3.4e38f; bi[j] = 0x7fffffff; }
    const float* xb = x_rec + (size_t)b * NR * 3;
#pragma unroll 1
    for (int base = 0; base < NR; base += 1024) {      // 4 points per thread per pass
        float d2v[4];
#pragma unroll
        for (int u = 0; u < 4; u++) {
            int r = base + u * 256 + tid;
            float dx = xb[r * 3 + 0] - px;
            float dy = xb[r * 3 + 1] - py;
            float dz = xb[r * 3 + 2] - pz;
            d2v[u] = dx * dx + dy * dy + dz * dz;
        }
#pragma unroll
        for (int u = 0; u < 4; u++) {
            float d2 = d2v[u];
            if (d2 < bd[KNN - 1]) {
                int r = base + u * 256 + tid;
                int p = KNN - 1;
                while (p > 0 && d2 < bd[p - 1]) { bd[p] = bd[p - 1]; bi[p] = bi[p - 1]; p--; }
                bd[p] = d2; bi[p] = r;
            }
        }
    }
#pragma unroll
    for (int j = 0; j < KNN; j++) { sd[tid * KNN + j] = bd[j]; si[tid * KNN + j] = bi[j]; }
    for (int stride = 128; stride >= 1; stride >>= 1) {
        __syncthreads();
        if (tid < stride) {
            float od[KNN]; int oi[KNN];
            int ia = 0, ib = 0;
#pragma unroll
            for (int o = 0; o < KNN; o++) {
                float da = sd[tid * KNN + ia], db = sd[(tid + stride) * KNN + ib];
                int xa = si[tid * KNN + ia], xb2 = si[(tid + stride) * KNN + ib];
                bool ta = (da < db) || (da == db && xa < xb2);
                if (ta) { od[o] = da; oi[o] = xa; ia++; }
                else    { od[o] = db; oi[o] = xb2; ib++; }
            }
#pragma unroll
            for (int o = 0; o < KNN; o++) { sd[tid * KNN + o] = od[o]; si[tid * KNN + o] = oi[o]; }
        }
    }
    __syncthreads();
    if (tid < KNN) { dk8[tid] = sqrtf(sd[tid]); id8[tid] = si[tid]; }
    __syncthreads();

    int j = tid;
    float a = 0.f;
#pragma unroll
    for (int t = 0; t < KNN; t++)
        a += h_rec[((size_t)b * NR + id8[t]) * FF + j];
    hm[j] = a * 0.125f;
    __syncthreads();

    float y = b_mlp[j];
#pragma unroll 16
    for (int i = 0; i < FF; i++) y += hm[i] * W_mlp[i * FF + j];
#pragma unroll
    for (int t = 0; t < KNN; t++) y += dk8[t] * W_mlp[(FF + t) * FF + j];
    y = y / (1.f + expf(-y));

    float s1 = y, s2 = y * y;
#pragma unroll
    for (int d = 16; d; d >>= 1) {
        s1 += __shfl_down_sync(0xffffffffu, s1, d);
        s2 += __shfl_down_sync(0xffffffffu, s2, d);
    }
    int lane = j & 31, w = j >> 5;
    if (lane == 0) { rbuf[w] = s1; rbuf[8 + w] = s2; }
    __syncthreads();
    if (j == 0) {
        float sa = 0.f, sb = 0.f;
#pragma unroll
        for (int w2 = 0; w2 < 8; w2++) { sa += rbuf[w2]; sb += rbuf[8 + w2]; }
        float mu = sa * (1.f / 256.f);
        mv[0] = mu;
        mv[1] = sb * (1.f / 256.f) - mu * mu;
    }
    __syncthreads();
    float mu = mv[0];
    float inv = rsqrtf(mv[1] + 1e-5f);
    out[BB * NK * 3 + bk * FF + j] = (y - mu) * inv * gamma[j] + beta[j];
}

// ---------------- launch ----------------
extern "C" void kernel_launch(void* const* d_in, const int* in_sizes, int n_in,
                              void* d_out, int out_size) {
    const float* h_rec = (const float*)d_in[0];
    const float* x_rec = (const float*)d_in[1];
    const float* h0_kp = (const float*)d_in[2];
    const float* W_src = (const float*)d_in[3];
    const float* W_mlp = (const float*)d_in[4];
    const float* b_mlp = (const float*)d_in[5];
    const float* gamma = (const float*)d_in[6];
    const float* beta  = (const float*)d_in[7];
    float* out = (float*)d_out;

    const int attn_smem = ATTN_SMEM_FLOATS * 4;
    const int v_smem = V_SMEM_FLOATS * 4;
    const int ft_smem = FT_SMEM_FLOATS * 4;
    cudaFuncSetAttribute(k_attn, cudaFuncAttributeMaxDynamicSharedMemorySize, attn_smem);
    cudaFuncSetAttribute(k_V, cudaFuncAttributeMaxDynamicSharedMemorySize, v_smem);
    cudaFuncSetAttribute(k_ftdst, cudaFuncAttributeMaxDynamicSharedMemorySize, ft_smem);

    k_ftdst<<<dim3(16, BB), 256, ft_smem>>>(h0_kp, W_src);      // launch 1
    k_V<<<dim3(16, BB), 256, v_smem>>>(W_src);                  // launch 2
    k_zeroS<<<(BB * NK * HH * 4 + 255) / 256, 256>>>();         // launch 3
    k_attn<<<dim3(32, BB), 256, attn_smem>>>(h_rec, x_rec);     // launch 4 -> profiled
    k_tail<<<BB * NK, 256>>>(x_rec, h_rec, W_mlp, b_mlp, gamma, beta, out);
}

// round 4
// speedup vs baseline: 1.4972x; 1.2945x over previous
#include <cuda_runtime.h>
#include <cuda_bf16.h>
#include <cstdint>

// ---------------- problem constants ----------------
#define BB   8
#define NR   4096
#define NK   20
#define FF   256
#define HH   4
#define KH   80        // NK*HH column count of fused V
#define KNN  8

// ---------------- device scratch ----------------
__device__ float g_ftdst[BB * NK * 1024];    // [b][k][h*256+d]
__device__ float g_V[BB * FF * KH];          // [b][f][kh], kh = k*4+h  (scaled 1/16)
__device__ float g_S[BB * NK * HH * 4];      // [b][k][h][{sumE, sumEx, sumEy, sumEz}]

// ---------------- f32x2 helpers ----------------
__device__ __forceinline__ unsigned long long pack2(float x, float y) {
    unsigned long long r;
    asm("mov.b64 %0, {%1, %2};" : "=l"(r) : "f"(x), "f"(y));
    return r;
}
__device__ __forceinline__ void unpack2(unsigned long long v, float& x, float& y) {
    asm("mov.b64 {%0, %1}, %2;" : "=f"(x), "=f"(y) : "l"(v));
}
__device__ __forceinline__ void fma2(unsigned long long& d, unsigned long long a, unsigned long long b) {
    asm("fma.rn.f32x2 %0, %1, %2, %0;" : "+l"(d) : "l"(a), "l"(b));
}

// ---------------- A1: ft_dst = h0_kp @ W_src (smem-staged W tile) ----------------
#define FT_SMEM_FLOATS (NK * FF + 256 * 65)
__global__ void __launch_bounds__(256) k_ftdst(const float* __restrict__ h0,
                                               const float* __restrict__ W) {
    extern __shared__ float sm[];
    float* hs = sm;             // [20][256]
    float* ws = sm + NK * FF;   // [256][65] padded
    int b = blockIdx.y, ct = blockIdx.x;
    if (ct == 0) {
        for (int i = threadIdx.x; i < FF * KH; i += 256) g_V[b * FF * KH + i] = 0.f;
    }
    for (int i = threadIdx.x; i < NK * FF; i += 256) hs[i] = h0[b * NK * FF + i];
#pragma unroll 8
    for (int i = threadIdx.x; i < 256 * 64; i += 256) {
        int f = i >> 6, c = i & 63;
        ws[f * 65 + c] = W[f * 1024 + ct * 64 + c];
    }
    __syncthreads();
    int cg = threadIdx.x & 63;
    int rgp = threadIdx.x >> 6;
    float acc[5] = {0.f, 0.f, 0.f, 0.f, 0.f};
#pragma unroll 8
    for (int f = 0; f < 256; f++) {
        float w = ws[f * 65 + cg];
#pragma unroll
        for (int q = 0; q < 5; q++) acc[q] += hs[(rgp * 5 + q) * 256 + f] * w;
    }
    int c = ct * 64 + cg;
#pragma unroll
    for (int q = 0; q < 5; q++)
        g_ftdst[(b * NK + rgp * 5 + q) * 1024 + c] = acc[q];
}

// ---------------- A2: V[b,f,kh] = (1/16) sum_d W[f,h*256+d] * ftdst[b,k,h*256+d] ----
#define V_SMEM_FLOATS (64 * 257 + NK * 256)
__global__ void __launch_bounds__(256) k_V(const float* __restrict__ W) {
    extern __shared__ float sm[];
    float* ws2 = sm;
    float* fts2 = sm + 64 * 257;
    int b = blockIdx.y;
    int ft = blockIdx.x >> 2, ds = blockIdx.x & 3;
    int fbase = ft * 64, dbase = ds * 64;
#pragma unroll 4
    for (int i = threadIdx.x; i < 64 * 256; i += 256) {
        int fi = i >> 8, rest = i & 255;
        int h = rest >> 6, dd = rest & 63;
        ws2[fi * 257 + rest] = W[(fbase + fi) * 1024 + h * 256 + dbase + dd];
    }
#pragma unroll 4
    for (int i = threadIdx.x; i < NK * 256; i += 256) {
        int rest = i & 255;
        int h = rest >> 6, dd = rest & 63;
        int k = i >> 8;
        fts2[i] = g_ftdst[b * 20480 + k * 1024 + h * 256 + dbase + dd];
    }
    __syncthreads();
    int fi = threadIdx.x & 63;
    int h  = threadIdx.x >> 6;
    float acc[NK];
#pragma unroll
    for (int j = 0; j < NK; j++) acc[j] = 0.f;
    const float* wp = ws2 + fi * 257 + h * 64;
    const float* fp = fts2 + h * 64;
#pragma unroll 2
    for (int dd = 0; dd < 64; dd++) {
        float w = wp[dd];
#pragma unroll
        for (int j = 0; j < NK; j++) acc[j] += w * fp[j * 256 + dd];
    }
    float* gv = g_V + b * (FF * KH) + (fbase + fi) * KH + h;
#pragma unroll
    for (int j = 0; j < NK; j++)
        atomicAdd(gv + j * 4, acc[j] * 0.0625f);
}

// ---------------- zero g_S (3rd launch so k_attn is the profiled 4th) ----------------
__global__ void k_zeroS() {
    int i = blockIdx.x * blockDim.x + threadIdx.x;
    if (i < BB * NK * HH * 4) g_S[i] = 0.f;
}

// ---------------- B: fused  a = h_rec @ V ; exp ; 4 moments ----------------
// grid (16, 8) = 128 blocks (single wave), 256 threads, 1 CTA/SM.
// Thread tile: 8 rows x 5 column-pairs (10 cols). 3 LDS feed 40 fma2 per f.
#define ATTN_VS   (256 * 96)
#define ATTN_RED  2560
#define ATTN_SMEM_FLOATS (ATTN_VS + ATTN_RED)
__global__ void __launch_bounds__(256, 1) k_attn(const float* __restrict__ h_rec,
                                                 const float* __restrict__ x_rec) {
    extern __shared__ float sm[];
    float* Vsp = sm;
    float* red = sm + ATTN_VS;
    int b = blockIdx.y;
    int tid = threadIdx.x;
    int lane = tid & 31, w = tid >> 5;
    int rg = tid >> 3, cg = tid & 7;

    // load + permute V: thread's 10 columns contiguous (padded to 12)
    const float* gV = g_V + b * (FF * KH);
    for (int t = tid; t < FF * KH; t += 256) {
        int f = t / 80, q = t % 80;
        int c2 = q / 10, j = q % 10;
        int ip = j >> 1, sub = j & 1;
        int c = ((c2 + 8 * ip) << 1) | sub;
        Vsp[f * 96 + c2 * 12 + j] = gV[f * 80 + c];
    }
    for (int t = tid; t < ATTN_RED; t += 256) red[t] = 0.f;
    __syncthreads();

    int rowbase = blockIdx.x * 256;
    int row0 = rowbase + rg * 8;                       // 8 rows per thread
    const float4* hp = (const float4*)(h_rec + ((size_t)b * NR + row0) * FF);
    // row r at hp + r*64 + f4

    unsigned long long acc[8][5];
#pragma unroll
    for (int r = 0; r < 8; r++)
#pragma unroll
        for (int i = 0; i < 5; i++) acc[r][i] = 0ull;

    const char* vbase = (const char*)(Vsp + cg * 12);
#pragma unroll 2
    for (int f4 = 0; f4 < 64; f4++) {
        float4 a[8];
#pragma unroll
        for (int r = 0; r < 8; r++) a[r] = __ldg(hp + r * 64 + f4);
#pragma unroll
        for (int e = 0; e < 4; e++) {
            const ulonglong2* vp = (const ulonglong2*)(vbase + (size_t)(f4 * 4 + e) * 384);
            ulonglong2 v01 = vp[0];
            ulonglong2 v23 = vp[1];
            unsigned long long v4 = *(const unsigned long long*)(vp + 2);
#pragma unroll
            for (int r = 0; r < 8; r++) {
                float h = (e == 0) ? a[r].x : (e == 1) ? a[r].y : (e == 2) ? a[r].z : a[r].w;
                unsigned long long H = pack2(h, h);
                fma2(acc[r][0], H, v01.x);
                fma2(acc[r][1], H, v01.y);
                fma2(acc[r][2], H, v23.x);
                fma2(acc[r][3], H, v23.y);
                fma2(acc[r][4], H, v4);
            }
        }
    }

    // epilogue: exp + 4 moments over this thread's 8 rows
    const float* xp = x_rec + ((size_t)b * NR + row0) * 3;
    float xr[8][3];
#pragma unroll
    for (int r = 0; r < 8; r++) {
        xr[r][0] = xp[r * 3 + 0];
        xr[r][1] = xp[r * 3 + 1];
        xr[r][2] = xp[r * 3 + 2];
    }
#pragma unroll
    for (int i = 0; i < 5; i++) {
        float al[8], ah[8];
#pragma unroll
        for (int r = 0; r < 8; r++) unpack2(acc[r][i], al[r], ah[r]);
#pragma unroll
        for (int sub = 0; sub < 2; sub++) {
            float v0 = 0.f, v1 = 0.f, v2 = 0.f, v3 = 0.f;
#pragma unroll
            for (int r = 0; r < 8; r++) {
                float e = expf(sub ? ah[r] : al[r]);
                v0 += e;
                v1 += e * xr[r][0];
                v2 += e * xr[r][1];
                v3 += e * xr[r][2];
            }
#pragma unroll
            for (int d = 16; d >= 8; d >>= 1) {
                v0 += __shfl_down_sync(0xffffffffu, v0, d);
                v1 += __shfl_down_sync(0xffffffffu, v1, d);
                v2 += __shfl_down_sync(0xffffffffu, v2, d);
                v3 += __shfl_down_sync(0xffffffffu, v3, d);
            }
            if (lane < 8) {
                float* rp = red + w * 320 + cg * 40 + (2 * i + sub) * 4;
                rp[0] += v0; rp[1] += v1; rp[2] += v2; rp[3] += v3;
            }
        }
    }
    __syncthreads();
    for (int v = tid; v < 320; v += 256) {
        int cg2 = v / 40, sidx = v % 40;
        float sum = 0.f;
#pragma unroll
        for (int w2 = 0; w2 < 8; w2++) sum += red[w2 * 320 + cg2 * 40 + sidx];
        int pair = sidx >> 2, stat = sidx & 3;
        int ii = pair >> 1, sub = pair & 1;
        int col = 2 * (cg2 + 8 * ii) + sub;
        atomicAdd(&g_S[b * 320 + col * 4 + stat], sum);
    }
}

// ---------------- tail: kp_pos + top-8 + gather/MLP/SiLU/LayerNorm ----------------
__global__ void __launch_bounds__(256) k_tail(const float* __restrict__ x_rec,
                                              const float* __restrict__ h_rec,
                                              const float* __restrict__ W_mlp,
                                              const float* __restrict__ b_mlp,
                                              const float* __restrict__ gamma,
                                              const float* __restrict__ beta,
                                              float* __restrict__ out) {
    __shared__ float sd[256 * KNN];
    __shared__ int   si[256 * KNN];
    __shared__ float kpos[3];
    __shared__ float hm[FF];
    __shared__ float dk8[KNN];
    __shared__ int   id8[KNN];
    __shared__ float rbuf[16];
    __shared__ float mv[2];
    int bk = blockIdx.x, b = bk / NK, tid = threadIdx.x;

    if (tid == 0) {
        float p0 = 0.f, p1 = 0.f, p2 = 0.f;
#pragma unroll
        for (int h = 0; h < HH; h++) {
            const float* S = g_S + bk * 16 + h * 4;
            float inv = 1.f / S[0];
            p0 += S[1] * inv; p1 += S[2] * inv; p2 += S[3] * inv;
        }
        p0 *= 0.25f; p1 *= 0.25f; p2 *= 0.25f;
        kpos[0] = p0; kpos[1] = p1; kpos[2] = p2;
        out[bk * 3 + 0] = p0; out[bk * 3 + 1] = p1; out[bk * 3 + 2] = p2;
    }
    __syncthreads();
    float px = kpos[0], py = kpos[1], pz = kpos[2];

    float bd[KNN]; int bi[KNN];
#pragma unroll
    for (int j = 0; j < KNN; j++) { bd[j] = 3.4e38f; bi[j] = 0x7fffffff; }
    const float* xb = x_rec + (size_t)b * NR * 3;
#pragma unroll 1
    for (int base = 0; base < NR; base += 1024) {
        float d2v[4];
#pragma unroll
        for (int u = 0; u < 4; u++) {
            int r = base + u * 256 + tid;
            float dx = xb[r * 3 + 0] - px;
            float dy = xb[r * 3 + 1] - py;
            float dz = xb[r * 3 + 2] - pz;
            d2v[u] = dx * dx + dy * dy + dz * dz;
        }
#pragma unroll
        for (int u = 0; u < 4; u++) {
            float d2 = d2v[u];
            if (d2 < bd[KNN - 1]) {
                int r = base + u * 256 + tid;
                int p = KNN - 1;
                while (p > 0 && d2 < bd[p - 1]) { bd[p] = bd[p - 1]; bi[p] = bi[p - 1]; p--; }
                bd[p] = d2; bi[p] = r;
            }
        }
    }
#pragma unroll
    for (int j = 0; j < KNN; j++) { sd[tid * KNN + j] = bd[j]; si[tid * KNN + j] = bi[j]; }
    for (int stride = 128; stride >= 1; stride >>= 1) {
        __syncthreads();
        if (tid < stride) {
            float od[KNN]; int oi[KNN];
            int ia = 0, ib = 0;
#pragma unroll
            for (int o = 0; o < KNN; o++) {
                float da = sd[tid * KNN + ia], db = sd[(tid + stride) * KNN + ib];
                int xa = si[tid * KNN + ia], xb2 = si[(tid + stride) * KNN + ib];
                bool ta = (da < db) || (da == db && xa < xb2);
                if (ta) { od[o] = da; oi[o] = xa; ia++; }
                else    { od[o] = db; oi[o] = xb2; ib++; }
            }
#pragma unroll
            for (int o = 0; o < KNN; o++) { sd[tid * KNN + o] = od[o]; si[tid * KNN + o] = oi[o]; }
        }
    }
    __syncthreads();
    if (tid < KNN) { dk8[tid] = sqrtf(sd[tid]); id8[tid] = si[tid]; }
    __syncthreads();

    int j = tid;
    float a = 0.f;
#pragma unroll
    for (int t = 0; t < KNN; t++)
        a += h_rec[((size_t)b * NR + id8[t]) * FF + j];
    hm[j] = a * 0.125f;
    __syncthreads();

    float y = b_mlp[j];
#pragma unroll 16
    for (int i = 0; i < FF; i++) y += hm[i] * W_mlp[i * FF + j];
#pragma unroll
    for (int t = 0; t < KNN; t++) y += dk8[t] * W_mlp[(FF + t) * FF + j];
    y = y / (1.f + expf(-y));

    float s1 = y, s2 = y * y;
#pragma unroll
    for (int d = 16; d; d >>= 1) {
        s1 += __shfl_down_sync(0xffffffffu, s1, d);
        s2 += __shfl_down_sync(0xffffffffu, s2, d);
    }
    int lane = j & 31, w = j >> 5;
    if (lane == 0) { rbuf[w] = s1; rbuf[8 + w] = s2; }
    __syncthreads();
    if (j == 0) {
        float sa = 0.f, sb = 0.f;
#pragma unroll
        for (int w2 = 0; w2 < 8; w2++) { sa += rbuf[w2]; sb += rbuf[8 + w2]; }
        float mu = sa * (1.f / 256.f);
        mv[0] = mu;
        mv[1] = sb * (1.f / 256.f) - mu * mu;
    }
    __syncthreads();
    float mu = mv[0];
    float inv = rsqrtf(mv[1] + 1e-5f);
    out[BB * NK * 3 + bk * FF + j] = (y - mu) * inv * gamma[j] + beta[j];
}

// ---------------- launch ----------------
extern "C" void kernel_launch(void* const* d_in, const int* in_sizes, int n_in,
                              void* d_out, int out_size) {
    const float* h_rec = (const float*)d_in[0];
    const float* x_rec = (const float*)d_in[1];
    const float* h0_kp = (const float*)d_in[2];
    const float* W_src = (const float*)d_in[3];
    const float* W_mlp = (const float*)d_in[4];
    const float* b_mlp = (const float*)d_in[5];
    const float* gamma = (const float*)d_in[6];
    const float* beta  = (const float*)d_in[7];
    float* out = (float*)d_out;

    const int attn_smem = ATTN_SMEM_FLOATS * 4;
    const int v_smem = V_SMEM_FLOATS * 4;
    const int ft_smem = FT_SMEM_FLOATS * 4;
    cudaFuncSetAttribute(k_attn, cudaFuncAttributeMaxDynamicSharedMemorySize, attn_smem);
    cudaFuncSetAttribute(k_V, cudaFuncAttributeMaxDynamicSharedMemorySize, v_smem);
    cudaFuncSetAttribute(k_ftdst, cudaFuncAttributeMaxDynamicSharedMemorySize, ft_smem);

    k_ftdst<<<dim3(16, BB), 256, ft_smem>>>(h0_kp, W_src);      // launch 1
    k_V<<<dim3(16, BB), 256, v_smem>>>(W_src);                  // launch 2
    k_zeroS<<<(BB * NK * HH * 4 + 255) / 256, 256>>>();         // launch 3
    k_attn<<<dim3(16, BB), 256, attn_smem>>>(h_rec, x_rec);     // launch 4 -> profiled
    k_tail<<<BB * NK, 256>>>(x_rec, h_rec, W_mlp, b_mlp, gamma, beta, out);
}